// round 10
// baseline (speedup 1.0000x reference)
#include <cuda_runtime.h>
#include <cuda_bf16.h>
#include <math.h>

// Problem dims
#define TT 512
#define BB 64
#define II 512
#define HH 512

// Phase-2: 128 blocks = 8 groups (8 batches) x 16 j-tiles (32 j each).
#define NBLK 128
#define GRPS 8
#define GBLK 16
#define JT   32
#define BT   8
#define HSTR 520            // h_sh row stride in floats (512 + 8 pad)
#define RSTR 37             // reduction row stride in floats

__device__ __align__(16) float g_hbuf[2 * BB * HH];
__device__ __align__(16) unsigned g_arrive[NBLK];   // zero-init; monotonic
__device__ __align__(16) unsigned g_xpcnt[TT];      // re-zeroed by init node

// ---- helpers -------------------------------------------------------------
__device__ __forceinline__ unsigned long long pack2(float x, float y) {
    unsigned long long r;
    asm("mov.b64 %0, {%1, %2};" : "=l"(r) : "f"(x), "f"(y));
    return r;
}
__device__ __forceinline__ float hadd2(unsigned long long v) {
    float lo, hi;
    asm("mov.b64 {%0, %1}, %2;" : "=f"(lo), "=f"(hi) : "l"(v));
    return lo + hi;
}
#define FMA2(c, a, b) \
    asm("fma.rn.f32x2 %0, %1, %2, %3;" : "=l"(c) : "l"(a), "l"(b), "l"(c))

__device__ __forceinline__ unsigned ld_acq(const unsigned* p) {
    unsigned v;
    asm volatile("ld.acquire.gpu.global.u32 %0, [%1];" : "=r"(v) : "l"(p));
    return v;
}
__device__ __forceinline__ void red_release_add1(unsigned* p) {
    asm volatile("red.release.gpu.global.add.u32 [%0], %1;"
                 :: "l"(p), "r"(1u) : "memory");
}

// ---------------------------------------------------------------------------
// Init node: re-zero xp readiness counters (runs before both kernels).
// ---------------------------------------------------------------------------
__global__ void init_flags_kernel() {
    g_xpcnt[threadIdx.x] = 0u;
}

// ---------------------------------------------------------------------------
// Phase 1 (concurrent producer): xp tile (t, n) = X[t] @ W^T slice.
// Tile M=64 (= one timestep), N=128, BK=16; 256 threads, 4x8 micro-tile.
// Reg-capped (<=85) so one CTA co-resides with a recurrence CTA per SM.
// After storing its tile: release-increment g_xpcnt[t]; xp(t) ready at 4.
// ---------------------------------------------------------------------------
__global__ void __launch_bounds__(256, 3) gemm_xp_kernel(
    const float* __restrict__ X, const float* __restrict__ W,
    float* __restrict__ C)
{
    const int K = II, N = HH;
    __shared__ __align__(16) float As[16][64];
    __shared__ __align__(16) float Bs[16][128];

    const int t  = blockIdx.y;
    const int bm = t * 64;
    const int bn = blockIdx.x * 128;
    const int tid = threadIdx.x;
    const int tx = tid & 15;    // cols tx*8..+8
    const int ty = tid >> 4;    // rows ty*4..+4

    float acc[4][8];
#pragma unroll
    for (int i = 0; i < 4; i++)
#pragma unroll
        for (int j = 0; j < 8; j++) acc[i][j] = 0.0f;

    for (int k0 = 0; k0 < K; k0 += 16) {
        {   // A: 64x16 = 256 float4, 1 per thread
            int r = tid >> 2;
            int c = (tid & 3) * 4;
            float4 va = *(const float4*)&X[(size_t)(bm + r) * K + k0 + c];
            As[c + 0][r] = va.x; As[c + 1][r] = va.y;
            As[c + 2][r] = va.z; As[c + 3][r] = va.w;
        }
#pragma unroll
        for (int l = 0; l < 2; l++) {   // B: 128x16 = 512 float4
            int idx = tid + l * 256;
            int r = idx >> 2;
            int c = (idx & 3) * 4;
            float4 vb = *(const float4*)&W[(size_t)(bn + r) * K + k0 + c];
            Bs[c + 0][r] = vb.x; Bs[c + 1][r] = vb.y;
            Bs[c + 2][r] = vb.z; Bs[c + 3][r] = vb.w;
        }
        __syncthreads();

#pragma unroll
        for (int kk = 0; kk < 16; kk++) {
            float a[4], b[8];
            *(float4*)&a[0] = *(const float4*)&As[kk][ty * 4];
            *(float4*)&b[0] = *(const float4*)&Bs[kk][tx * 8];
            *(float4*)&b[4] = *(const float4*)&Bs[kk][tx * 8 + 4];
#pragma unroll
            for (int i = 0; i < 4; i++)
#pragma unroll
                for (int j = 0; j < 8; j++)
                    acc[i][j] = fmaf(a[i], b[j], acc[i][j]);
        }
        __syncthreads();
    }

#pragma unroll
    for (int i = 0; i < 4; i++) {
        int row = bm + ty * 4 + i;
        float4 v0 = make_float4(acc[i][0], acc[i][1], acc[i][2], acc[i][3]);
        float4 v1 = make_float4(acc[i][4], acc[i][5], acc[i][6], acc[i][7]);
        *(float4*)&C[(size_t)row * N + bn + tx * 8]     = v0;
        *(float4*)&C[(size_t)row * N + bn + tx * 8 + 4] = v1;
    }

    __threadfence();
    __syncthreads();
    if (tid == 0) red_release_add1(&g_xpcnt[t]);
}

// ---------------------------------------------------------------------------
// Phase 2 (concurrent consumer): EXACT R5 engine (1511us measured) plus a
// per-step acquire-poll on g_xpcnt[t] before reading xp.
// ---------------------------------------------------------------------------
__global__ void __launch_bounds__(256) rnn_recurrence_kernel(
    const float* __restrict__ w_hh, float* __restrict__ out, int has_last)
{
    extern __shared__ __align__(16) float smem[];
    float* h_sh = smem;                       // [BT][HSTR] = 8 x 520
    float* red  = smem + BT * HSTR;           // [256][RSTR] = 256 x 37

    const int tid = threadIdx.x;
    const int bid = blockIdx.x;
    const int grp = bid >> 4;
    const int jt  = bid & 15;
    const int b0  = grp * BT;
    const int j0  = jt * JT;

    const int ks = tid >> 3;       // 0..31
    const int jp = tid & 7;        // 0..7
    const int kbase = ks * 16;
    const int cxor = (ks & 2) << 1;

    __shared__ unsigned s_base;
    if (tid == 0) s_base = *((volatile unsigned*)&g_arrive[bid]);

    // ---- load W slab into registers
    unsigned long long wreg[4][8];
#pragma unroll
    for (int jj = 0; jj < 4; jj++) {
        const float* wr = &w_hh[(size_t)(j0 + jp * 4 + jj) * HH + kbase];
#pragma unroll
        for (int q = 0; q < 4; q++) {
            float4 v = *(const float4*)&wr[q * 4];
            wreg[jj][q * 2 + 0] = pack2(v.x, v.y);
            wreg[jj][q * 2 + 1] = pack2(v.z, v.w);
        }
    }
    __syncthreads();
    const unsigned base = s_base;

    const int gj = j0 + (tid & 31);
    const int gb = b0 + (tid >> 5);

    float* __restrict__ hall  = out;
    float* __restrict__ hlast = out + (size_t)TT * BB * HH;

    for (int t = 0; t < TT; t++) {
        // wait until xp(t) produced (4 n-tiles), then prefetch own xp
        while (ld_acq(&g_xpcnt[t]) < 4u) __nanosleep(64);
        float xp = hall[((size_t)t * BB + gb) * HH + gj];

        float hsum = 0.0f;
        if (t > 0) {
            // ---- group barrier: wait for all 16 group blocks at step t-1
            if (tid < 32) {
                const unsigned tgt = base + (unsigned)t;
                const unsigned* fl = &g_arrive[grp * GBLK + (tid & 15)];
                for (;;) {
                    unsigned v = (tid < 16) ? __ldcg(fl) : tgt;
                    if (__all_sync(0xffffffffu, v >= tgt)) break;
                    __nanosleep(32);
                }
                __threadfence();
            }
            __syncthreads();

            // ---- stage h(t-1) slice [8 b][512 k] into h_sh (XOR swizzle)
            {
                const int prev = (t - 1) & 1;
                const float4* src = (const float4*)&g_hbuf[
                    (size_t)prev * BB * HH + (size_t)b0 * HH];
#pragma unroll
                for (int r = 0; r < 4; r++) {
                    int idx = tid + r * 256;
                    int b  = idx >> 7;
                    int k4 = idx & 127;
                    float4 v = __ldcg(&src[(size_t)b * 128 + k4]);
                    int off = b * HSTR + ((k4 * 4) ^ (((k4 >> 3) & 1) << 2));
                    *(float4*)&h_sh[off] = v;
                }
            }
            __syncthreads();

            // ---- compute: acc[jj][bb] over 16 k (f32x2 pairs)
            unsigned long long acc[4][8];
#pragma unroll
            for (int jj = 0; jj < 4; jj++)
#pragma unroll
                for (int bb = 0; bb < 8; bb++) acc[jj][bb] = 0ULL;

#pragma unroll
            for (int q = 0; q < 4; q++) {
                const int koff = kbase + ((q * 4) ^ cxor);
#pragma unroll
                for (int bb = 0; bb < 8; bb++) {
                    ulonglong2 hv = *(const ulonglong2*)&h_sh[
                        bb * HSTR + koff];
#pragma unroll
                    for (int jj = 0; jj < 4; jj++) {
                        FMA2(acc[jj][bb], wreg[jj][q * 2 + 0], hv.x);
                        FMA2(acc[jj][bb], wreg[jj][q * 2 + 1], hv.y);
                    }
                }
            }

            // ---- partials -> red[row][ks], row = bb*32 + jp*4 + jj
#pragma unroll
            for (int jj = 0; jj < 4; jj++)
#pragma unroll
                for (int bb = 0; bb < 8; bb++)
                    red[(bb * 32 + jp * 4 + jj) * RSTR + ks] =
                        hadd2(acc[jj][bb]);
            __syncthreads();

            const float* rr = &red[tid * RSTR];
            float s = 0.0f;
#pragma unroll
            for (int i = 0; i < 32; i++) s += rr[i];
            hsum = s;
        }

        float h = tanhf(xp + hsum);

        g_hbuf[((size_t)(t & 1) * BB + gb) * HH + gj] = h;

        if (t != TT - 1) {
            __syncthreads();
            if (tid == 0) {
                __threadfence();
                *((volatile unsigned*)&g_arrive[bid]) = base + 1u + (unsigned)t;
            }
        }

        hall[((size_t)t * BB + gb) * HH + gj] = h;
        if (has_last && t == TT - 1)
            hlast[(size_t)gb * HH + gj] = h;
    }
}

// ---------------------------------------------------------------------------
// Launch: graph = init -> { gemm (stream s2)  ||  recurrence (main) } -> join
// ---------------------------------------------------------------------------
extern "C" void kernel_launch(void* const* d_in, const int* in_sizes, int n_in,
                              void* d_out, int out_size) {
    const float* x    = (const float*)d_in[0];   // (T, B, I)
    const float* w_ih = (const float*)d_in[1];   // (H, I)
    const float* w_hh = (const float*)d_in[2];   // (H, H)
    float* out = (float*)d_out;

    int smem_bytes = (BT * HSTR + 256 * RSTR) * (int)sizeof(float); // ~54KB
    cudaFuncSetAttribute(rnn_recurrence_kernel,
                         cudaFuncAttributeMaxDynamicSharedMemorySize, smem_bytes);
    int has_last = (out_size >= TT * BB * HH + BB * HH) ? 1 : 0;

    // fork/join plumbing (leaked per call: few calls total, host-side only)
    cudaStream_t s2;
    cudaStreamCreateWithFlags(&s2, cudaStreamNonBlocking);
    cudaEvent_t eFork, eJoin;
    cudaEventCreateWithFlags(&eFork, cudaEventDisableTiming);
    cudaEventCreateWithFlags(&eJoin, cudaEventDisableTiming);

    // init node (re-zero xp counters every replay)
    init_flags_kernel<<<1, TT>>>();

    // fork: gemm on s2, concurrent with recurrence on main stream
    cudaEventRecord(eFork, 0);
    cudaStreamWaitEvent(s2, eFork, 0);
    gemm_xp_kernel<<<dim3(HH / 128, TT), 256, 0, s2>>>(x, w_ih, out);
    cudaEventRecord(eJoin, s2);

    rnn_recurrence_kernel<<<NBLK, 256, smem_bytes>>>(w_hh, out, has_last);

    // join: main stream (graph sink) depends on gemm completion
    cudaStreamWaitEvent(0, eJoin, 0);
}

// round 11
// speedup vs baseline: 1.0455x; 1.0455x over previous
#include <cuda_runtime.h>
#include <cuda_bf16.h>
#include <math.h>

// Problem dims
#define TT 512
#define BB 64
#define II 512
#define HH 512

// 128 blocks = 8 groups (8 batches) x 16 j-tiles (32 j each).
#define NBLK 128
#define GRPS 8
#define GBLK 16
#define JT   32
#define BT   8
#define HSTR 520            // staging row stride in floats (512 + 8 pad)
#define RSTR 37             // reduction row stride in floats

__device__ __align__(16) float g_hbuf[2 * BB * HH];
__device__ __align__(16) unsigned g_arrive[NBLK];   // zero-init; monotonic

// ---- f32x2 helpers -------------------------------------------------------
__device__ __forceinline__ unsigned long long pack2(float x, float y) {
    unsigned long long r;
    asm("mov.b64 %0, {%1, %2};" : "=l"(r) : "f"(x), "f"(y));
    return r;
}
__device__ __forceinline__ float hadd2(unsigned long long v) {
    float lo, hi;
    asm("mov.b64 {%0, %1}, %2;" : "=f"(lo), "=f"(hi) : "l"(v));
    return lo + hi;
}
#define FMA2(c, a, b) \
    asm("fma.rn.f32x2 %0, %1, %2, %3;" : "=l"(c) : "l"(a), "l"(b), "l"(c))

// ---------------------------------------------------------------------------
// Fused RNN: one persistent kernel. Per step t:
//   [x phase -- no cross-CTA dependency, overlaps the group-barrier window]
//     stage x(t) slice -> x_sh; compute acc = W_ih-slab . x
//   [h phase]
//     group barrier (peer flags for t-1); stage h(t-1) -> h_sh;
//     accumulate acc += W_hh-slab . h
//   split-k reduction via smem; h = tanh(sum); exchange via g_hbuf + flags.
// Thread (ks=tid>>3, jp=tid&7) owns BOTH W slabs for rows j0+jp*4+jj,
// k in [ks*16, ks*16+16), as packed f32x2 registers.
// ---------------------------------------------------------------------------
__global__ void __launch_bounds__(256) rnn_fused_kernel(
    const float* __restrict__ X, const float* __restrict__ w_ih,
    const float* __restrict__ w_hh, float* __restrict__ out, int has_last)
{
    extern __shared__ __align__(16) float smem[];
    float* x_sh = smem;                        // [BT][HSTR]
    float* h_sh = smem + BT * HSTR;            // [BT][HSTR]
    float* red  = smem + 2 * BT * HSTR;        // [256][RSTR]

    const int tid = threadIdx.x;
    const int bid = blockIdx.x;
    const int grp = bid >> 4;
    const int jt  = bid & 15;
    const int b0  = grp * BT;
    const int j0  = jt * JT;

    const int ks = tid >> 3;       // 0..31
    const int jp = tid & 7;        // 0..7
    const int kbase = ks * 16;
    const int cxor = (ks & 2) << 1;

    __shared__ unsigned s_base;
    if (tid == 0) s_base = *((volatile unsigned*)&g_arrive[bid]);

    // ---- load both W slabs into registers (packed f32x2)
    unsigned long long whh[4][8], wih[4][8];
#pragma unroll
    for (int jj = 0; jj < 4; jj++) {
        const float* wr = &w_hh[(size_t)(j0 + jp * 4 + jj) * HH + kbase];
        const float* wi = &w_ih[(size_t)(j0 + jp * 4 + jj) * II + kbase];
#pragma unroll
        for (int q = 0; q < 4; q++) {
            float4 v = *(const float4*)&wr[q * 4];
            whh[jj][q * 2 + 0] = pack2(v.x, v.y);
            whh[jj][q * 2 + 1] = pack2(v.z, v.w);
            float4 u = *(const float4*)&wi[q * 4];
            wih[jj][q * 2 + 0] = pack2(u.x, u.y);
            wih[jj][q * 2 + 1] = pack2(u.z, u.w);
        }
    }
    __syncthreads();
    const unsigned base = s_base;

    const int gj = j0 + (tid & 31);
    const int gb = b0 + (tid >> 5);

    float* __restrict__ hall  = out;
    float* __restrict__ hlast = out + (size_t)TT * BB * HH;
    const float4* __restrict__ X4 = (const float4*)X;

    for (int t = 0; t < TT; t++) {
        // ================= x phase (independent of peers) =================
        // stage x(t) slice [8 b][512 k] into x_sh (XOR swizzle)
#pragma unroll
        for (int r = 0; r < 4; r++) {
            int idx = tid + r * 256;
            int b  = idx >> 7;
            int k4 = idx & 127;
            float4 v = __ldg(&X4[((size_t)t * BB + b0 + b) * 128 + k4]);
            int off = b * HSTR + ((k4 * 4) ^ (((k4 >> 3) & 1) << 2));
            *(float4*)&x_sh[off] = v;
        }
        __syncthreads();

        unsigned long long acc[4][8];
#pragma unroll
        for (int jj = 0; jj < 4; jj++)
#pragma unroll
            for (int bb = 0; bb < 8; bb++) acc[jj][bb] = 0ULL;

#pragma unroll
        for (int q = 0; q < 4; q++) {
            const int koff = kbase + ((q * 4) ^ cxor);
#pragma unroll
            for (int bb = 0; bb < 8; bb++) {
                ulonglong2 xv = *(const ulonglong2*)&x_sh[bb * HSTR + koff];
#pragma unroll
                for (int jj = 0; jj < 4; jj++) {
                    FMA2(acc[jj][bb], wih[jj][q * 2 + 0], xv.x);
                    FMA2(acc[jj][bb], wih[jj][q * 2 + 1], xv.y);
                }
            }
        }

        // ================= h phase (needs peers' h(t-1)) ==================
        if (t > 0) {
            // group barrier: wait for all 16 group blocks at step t-1
            if (tid < 32) {
                const unsigned tgt = base + (unsigned)t;
                const unsigned* fl = &g_arrive[grp * GBLK + (tid & 15)];
                for (;;) {
                    unsigned v = (tid < 16) ? __ldcg(fl) : tgt;
                    if (__all_sync(0xffffffffu, v >= tgt)) break;
                    __nanosleep(32);
                }
                __threadfence();
            }
            __syncthreads();

            // stage h(t-1) slice into h_sh (XOR swizzle)
            {
                const int prev = (t - 1) & 1;
                const float4* src = (const float4*)&g_hbuf[
                    (size_t)prev * BB * HH + (size_t)b0 * HH];
#pragma unroll
                for (int r = 0; r < 4; r++) {
                    int idx = tid + r * 256;
                    int b  = idx >> 7;
                    int k4 = idx & 127;
                    float4 v = __ldcg(&src[(size_t)b * 128 + k4]);
                    int off = b * HSTR + ((k4 * 4) ^ (((k4 >> 3) & 1) << 2));
                    *(float4*)&h_sh[off] = v;
                }
            }
            __syncthreads();

#pragma unroll
            for (int q = 0; q < 4; q++) {
                const int koff = kbase + ((q * 4) ^ cxor);
#pragma unroll
                for (int bb = 0; bb < 8; bb++) {
                    ulonglong2 hv = *(const ulonglong2*)&h_sh[bb * HSTR + koff];
#pragma unroll
                    for (int jj = 0; jj < 4; jj++) {
                        FMA2(acc[jj][bb], whh[jj][q * 2 + 0], hv.x);
                        FMA2(acc[jj][bb], whh[jj][q * 2 + 1], hv.y);
                    }
                }
            }
        }

        // ================= reduction + activation + exchange ==============
#pragma unroll
        for (int jj = 0; jj < 4; jj++)
#pragma unroll
            for (int bb = 0; bb < 8; bb++)
                red[(bb * 32 + jp * 4 + jj) * RSTR + ks] = hadd2(acc[jj][bb]);
        __syncthreads();

        const float* rr = &red[tid * RSTR];
        float s = 0.0f;
#pragma unroll
        for (int i = 0; i < 32; i++) s += rr[i];

        float h = tanhf(s);

        g_hbuf[((size_t)(t & 1) * BB + gb) * HH + gj] = h;

        if (t != TT - 1) {
            __syncthreads();               // hbuf stores issued; red/x_sh free
            if (tid == 0) {
                __threadfence();
                *((volatile unsigned*)&g_arrive[bid]) = base + 1u + (unsigned)t;
            }
        }

        hall[((size_t)t * BB + gb) * HH + gj] = h;
        if (has_last && t == TT - 1)
            hlast[(size_t)gb * HH + gj] = h;
    }
}

// ---------------------------------------------------------------------------
extern "C" void kernel_launch(void* const* d_in, const int* in_sizes, int n_in,
                              void* d_out, int out_size) {
    const float* x    = (const float*)d_in[0];   // (T, B, I)
    const float* w_ih = (const float*)d_in[1];   // (H, I)
    const float* w_hh = (const float*)d_in[2];   // (H, H)
    float* out = (float*)d_out;

    int smem_bytes = (2 * BT * HSTR + 256 * RSTR) * (int)sizeof(float); // ~71KB
    cudaFuncSetAttribute(rnn_fused_kernel,
                         cudaFuncAttributeMaxDynamicSharedMemorySize, smem_bytes);
    int has_last = (out_size >= TT * BB * HH + BB * HH) ? 1 : 0;
    rnn_fused_kernel<<<NBLK, 256, smem_bytes>>>(x, w_ih, w_hh, out, has_last);
}

// round 12
// speedup vs baseline: 1.1403x; 1.0906x over previous
#include <cuda_runtime.h>
#include <cuda_bf16.h>
#include <math.h>

// Problem dims
#define TT 512
#define BB 64
#define II 512
#define HH 512

// Phase-2: 128 blocks = 16 groups (4 batches) x 8 j-tiles (64 j each).
#define NBLK 128
#define GRPS 16
#define GBLK 8
#define JT   64
#define BT   4
#define HSTR 520            // h_sh row stride in floats (512 + 8 pad)
#define RSTR 17             // reduction row stride in floats

__device__ __align__(16) float g_hbuf[2 * BB * HH];
__device__ __align__(16) unsigned g_arrive[NBLK];   // zero-init; monotonic

// ---- f32x2 helpers -------------------------------------------------------
__device__ __forceinline__ unsigned long long pack2(float x, float y) {
    unsigned long long r;
    asm("mov.b64 %0, {%1, %2};" : "=l"(r) : "f"(x), "f"(y));
    return r;
}
__device__ __forceinline__ float hadd2(unsigned long long v) {
    float lo, hi;
    asm("mov.b64 {%0, %1}, %2;" : "=f"(lo), "=f"(hi) : "l"(v));
    return lo + hi;
}
#define FMA2(c, a, b) \
    asm("fma.rn.f32x2 %0, %1, %2, %3;" : "=l"(c) : "l"(a), "l"(b), "l"(c))

// ---------------------------------------------------------------------------
// Phase 1: xp = X @ W^T  (M=32768, N=512, K=512), 128x128 tile, 8x8 micro.
// (Exact R5 kernel, measured ~430us.)
// ---------------------------------------------------------------------------
__global__ void __launch_bounds__(256) gemm_xp_kernel(
    const float* __restrict__ X, const float* __restrict__ W,
    float* __restrict__ C)
{
    const int K = II, N = HH;
    __shared__ __align__(16) float As[16][128];
    __shared__ __align__(16) float Bs[16][128];

    const int bm = blockIdx.x * 128;
    const int bn = blockIdx.y * 128;
    const int tid = threadIdx.x;
    const int tx = tid & 15;
    const int ty = tid >> 4;

    float acc[8][8];
#pragma unroll
    for (int i = 0; i < 8; i++)
#pragma unroll
        for (int j = 0; j < 8; j++) acc[i][j] = 0.0f;

    for (int k0 = 0; k0 < K; k0 += 16) {
#pragma unroll
        for (int l = 0; l < 2; l++) {
            int idx = tid + l * 256;
            int r = idx >> 2;
            int c = (idx & 3) * 4;
            float4 va = *(const float4*)&X[(size_t)(bm + r) * K + k0 + c];
            As[c + 0][r] = va.x; As[c + 1][r] = va.y;
            As[c + 2][r] = va.z; As[c + 3][r] = va.w;
            float4 vb = *(const float4*)&W[(size_t)(bn + r) * K + k0 + c];
            Bs[c + 0][r] = vb.x; Bs[c + 1][r] = vb.y;
            Bs[c + 2][r] = vb.z; Bs[c + 3][r] = vb.w;
        }
        __syncthreads();

#pragma unroll
        for (int kk = 0; kk < 16; kk++) {
            float a[8], b[8];
            *(float4*)&a[0] = *(const float4*)&As[kk][ty * 8];
            *(float4*)&a[4] = *(const float4*)&As[kk][ty * 8 + 4];
            *(float4*)&b[0] = *(const float4*)&Bs[kk][tx * 8];
            *(float4*)&b[4] = *(const float4*)&Bs[kk][tx * 8 + 4];
#pragma unroll
            for (int i = 0; i < 8; i++)
#pragma unroll
                for (int j = 0; j < 8; j++)
                    acc[i][j] = fmaf(a[i], b[j], acc[i][j]);
        }
        __syncthreads();
    }

#pragma unroll
    for (int i = 0; i < 8; i++) {
        int row = bm + ty * 8 + i;
        float4 v0 = make_float4(acc[i][0], acc[i][1], acc[i][2], acc[i][3]);
        float4 v1 = make_float4(acc[i][4], acc[i][5], acc[i][6], acc[i][7]);
        *(float4*)&C[(size_t)row * N + bn + tx * 8]     = v0;
        *(float4*)&C[(size_t)row * N + bn + tx * 8 + 4] = v1;
    }
}

// ---------------------------------------------------------------------------
// Phase 2: persistent recurrence, small-group topology.
//   bid = grp*8 + jt;  grp 0..15 owns batches [grp*4, grp*4+4); jt 0..7 owns
//   j in [jt*64, jt*64+64). Thread (ks = tid>>4 in 0..15, jp = tid&15):
//   W_hh rows j0+jp*4+jj (jj 0..3), k in [ks*32, ks*32+32) in registers
//   (128 floats packed f32x2). Computes acc[4j][4b]; 16-way split-k reduced
//   via stride-17 smem. 8-flag group barrier; h exchange via g_hbuf (L2).
//   h_sh XOR-4 swizzle: store (k4*4)^(((k4>>3)&1)<<2); read offset
//   (q*4)^cxor with cxor=(ks&1)<<2 (bit3 of k4 = ks bit0; q in 0..7).
// ---------------------------------------------------------------------------
__global__ void __launch_bounds__(256) rnn_recurrence_kernel(
    const float* __restrict__ w_hh, float* __restrict__ out, int has_last)
{
    __shared__ __align__(16) float h_sh[BT][HSTR];     // 4 x 520 = 8.3KB
    __shared__ __align__(16) float red[256 * RSTR];    // 17.4KB

    const int tid = threadIdx.x;
    const int bid = blockIdx.x;
    const int grp = bid >> 3;          // 0..15
    const int jt  = bid & 7;           // 0..7
    const int b0  = grp * BT;
    const int j0  = jt * JT;

    const int ks = tid >> 4;       // 0..15 (32 k each)
    const int jp = tid & 15;       // 0..15 (4 j each)
    const int kbase = ks * 32;
    const int cxor = (ks & 1) << 2;

    __shared__ unsigned s_base;
    if (tid == 0) s_base = *((volatile unsigned*)&g_arrive[bid]);

    // ---- W slab in registers: whh[jj][2q+i] = (w[j][k], w[j][k+1]) pairs
    unsigned long long whh[4][16];
#pragma unroll
    for (int jj = 0; jj < 4; jj++) {
        const float* wr = &w_hh[(size_t)(j0 + jp * 4 + jj) * HH + kbase];
#pragma unroll
        for (int q = 0; q < 8; q++) {
            float4 v = *(const float4*)&wr[q * 4];
            whh[jj][q * 2 + 0] = pack2(v.x, v.y);
            whh[jj][q * 2 + 1] = pack2(v.z, v.w);
        }
    }
    __syncthreads();
    const unsigned base = s_base;

    // output mapping (coalesced): oj = tid&63, ob = tid>>6
    const int gj = j0 + (tid & 63);
    const int gb = b0 + (tid >> 6);

    float* __restrict__ hall  = out;
    float* __restrict__ hlast = out + (size_t)TT * BB * HH;

    for (int t = 0; t < TT; t++) {
        // prefetch xp (own slice; no cross-block hazard)
        float xp = hall[((size_t)t * BB + gb) * HH + gj];

        float hsum = 0.0f;
        if (t > 0) {
            // ---- group barrier: wait for all 8 group blocks at step t-1
            if (tid < 32) {
                const unsigned tgt = base + (unsigned)t;
                const unsigned* fl = &g_arrive[grp * GBLK + (tid & 7)];
                for (;;) {
                    unsigned v = (tid < GBLK) ? __ldcg(fl) : tgt;
                    if (__all_sync(0xffffffffu, v >= tgt)) break;
                    __nanosleep(32);
                }
                __threadfence();
            }
            __syncthreads();

            // ---- stage h(t-1) slice [4 b][512 k] into h_sh (XOR swizzle)
            {
                const int prev = (t - 1) & 1;
                const float4* src = (const float4*)&g_hbuf[
                    (size_t)prev * BB * HH + (size_t)b0 * HH];
#pragma unroll
                for (int r = 0; r < 2; r++) {
                    int idx = tid + r * 256;       // 0..511
                    int b  = idx >> 7;             // 0..3
                    int k4 = idx & 127;
                    float4 v = __ldcg(&src[(size_t)b * 128 + k4]);
                    int off = b * HSTR + ((k4 * 4) ^ (((k4 >> 3) & 1) << 2));
                    *(float4*)&h_sh[0][off] = v;
                }
            }
            __syncthreads();

            // ---- compute: acc[jj][bb] over 32 k (f32x2 pairs)
            unsigned long long acc[4][4];
#pragma unroll
            for (int jj = 0; jj < 4; jj++)
#pragma unroll
                for (int bb = 0; bb < 4; bb++) acc[jj][bb] = 0ULL;

#pragma unroll
            for (int q = 0; q < 8; q++) {
                const int koff = kbase + ((q * 4) ^ cxor);
#pragma unroll
                for (int bb = 0; bb < 4; bb++) {
                    ulonglong2 hv = *(const ulonglong2*)&h_sh[bb][koff];
#pragma unroll
                    for (int jj = 0; jj < 4; jj++) {
                        FMA2(acc[jj][bb], whh[jj][q * 2 + 0], hv.x);
                        FMA2(acc[jj][bb], whh[jj][q * 2 + 1], hv.y);
                    }
                }
            }

            // ---- partials -> red[row][ks], row = bb*64 + jp*4 + jj
#pragma unroll
            for (int jj = 0; jj < 4; jj++)
#pragma unroll
                for (int bb = 0; bb < 4; bb++)
                    red[(bb * 64 + jp * 4 + jj) * RSTR + ks] =
                        hadd2(acc[jj][bb]);
            __syncthreads();

            // ---- thread o sums its row (row index == o); stride 17
            // scalar reads: banks 17*tid+i, consecutive tid 17 apart -> clean
            const float* rr = &red[tid * RSTR];
            float s0 = 0.f, s1 = 0.f, s2 = 0.f, s3 = 0.f;
#pragma unroll
            for (int i = 0; i < 16; i += 4) {
                s0 += rr[i + 0];
                s1 += rr[i + 1];
                s2 += rr[i + 2];
                s3 += rr[i + 3];
            }
            hsum = (s0 + s1) + (s2 + s3);
        }

        float h = tanhf(xp + hsum);

        // state store first, then signal (hall store off critical path)
        g_hbuf[((size_t)(t & 1) * BB + gb) * HH + gj] = h;

        if (t != TT - 1) {
            __syncthreads();               // all g_hbuf stores issued; red free
            if (tid == 0) {
                __threadfence();
                *((volatile unsigned*)&g_arrive[bid]) = base + 1u + (unsigned)t;
            }
        }

        hall[((size_t)t * BB + gb) * HH + gj] = h;
        if (has_last && t == TT - 1)
            hlast[(size_t)gb * HH + gj] = h;
    }
}

// ---------------------------------------------------------------------------
extern "C" void kernel_launch(void* const* d_in, const int* in_sizes, int n_in,
                              void* d_out, int out_size) {
    const float* x    = (const float*)d_in[0];   // (T, B, I)
    const float* w_ih = (const float*)d_in[1];   // (H, I)
    const float* w_hh = (const float*)d_in[2];   // (H, H)
    float* out = (float*)d_out;

    dim3 g1((TT * BB) / 128, HH / 128);
    gemm_xp_kernel<<<g1, 256>>>(x, w_ih, out);

    int has_last = (out_size >= TT * BB * HH + BB * HH) ? 1 : 0;
    rnn_recurrence_kernel<<<NBLK, 256>>>(w_hh, out, has_last);
}